// round 14
// baseline (speedup 1.0000x reference)
#include <cuda_runtime.h>
#include <cuda_bf16.h>
#include <cstdint>

// ---------------------------------------------------------------------------
// MobileAttention3D: B=2, C=256, D=32, H=W=32, NH=8, KD=VD=64
//
// R14: qkv & proj GEMMs on TF32 mma.sync (m16n8k8) — 1x fundamental work
//      instead of 3x bf16-split; x consumed raw fp32 (cvt_x deleted);
//      proj input g_Op is a single fp32 (tf32-rounded) stream; av epilogue
//      writes it directly (no pairing pass, no V smem).
// scores_mma / softmax / qkv epilogue (bf16-pair Q/K) unchanged (proven).
// ---------------------------------------------------------------------------

#define NPOS 32768

__device__ float    g_V  [2*32*65536];    // [b][j][e][sigma] (shuffled)
__device__ float    g_Ap [64*16*1024];    // partial logits [fc][bn][i*32+j]
__device__ float    g_A  [16*1024];       // softmaxed attn
__device__ float    g_Op [2*512*32768];   // proj input fp32(tf32) [b][e][p']
__device__ float    g_wqt[256*640];       // qkv W tf32 [k][oc]
__device__ float    g_wpt[512*256];       // proj W tf32 [k][oc]
__device__ uint32_t g_Qh [2*8*32*32768];  // Q hi pairs [(bn*32+i)][fp]
__device__ uint32_t g_Ql [2*8*32*32768];
__device__ uint32_t g_Kh [2*32*32768];    // K hi pairs [(b*32+j)][fp]
__device__ uint32_t g_Kl [2*32*32768];

// ---- helpers ----
__device__ __forceinline__ float tf32r(float x) {
    float y;
    asm("cvt.rna.tf32.f32 %0, %1;" : "=f"(y) : "f"(x));
    return y;
}
__device__ __forceinline__ uint32_t tf32r_u(uint32_t v) {
    float y;
    asm("cvt.rna.tf32.f32 %0, %1;" : "=f"(y) : "f"(__uint_as_float(v)));
    return __float_as_uint(y);
}
// Truncation bf16 split (proven): hi = top16 bits, lo = x - hi (exact), PRMT-packed.
__device__ __forceinline__ void pack2(float a, float b, uint32_t& hi, uint32_t& lo) {
    const uint32_t au = __float_as_uint(a), bu = __float_as_uint(b);
    const float ah = __uint_as_float(au & 0xFFFF0000u);
    const float bh = __uint_as_float(bu & 0xFFFF0000u);
    hi = __byte_perm(au, bu, 0x7632);
    lo = __byte_perm(__float_as_uint(a - ah), __float_as_uint(b - bh), 0x7632);
}
__device__ __forceinline__ uint32_t smem_u32(const void* p) {
    uint32_t a;
    asm("{ .reg .u64 t; cvta.to.shared.u64 t, %1; cvt.u32.u64 %0, t; }" : "=r"(a) : "l"(p));
    return a;
}

#define MMA16816(d, a, bf) \
    asm volatile("mma.sync.aligned.m16n8k16.row.col.f32.bf16.bf16.f32 " \
        "{%0,%1,%2,%3}, {%4,%5,%6,%7}, {%8,%9}, {%0,%1,%2,%3};" \
        : "+f"((d)[0]), "+f"((d)[1]), "+f"((d)[2]), "+f"((d)[3]) \
        : "r"((a)[0]), "r"((a)[1]), "r"((a)[2]), "r"((a)[3]), \
          "r"((bf)[0]), "r"((bf)[1]))

#define MMAT(d, a, bf) \
    asm volatile("mma.sync.aligned.m16n8k8.row.col.f32.tf32.tf32.f32 " \
        "{%0,%1,%2,%3}, {%4,%5,%6,%7}, {%8,%9}, {%0,%1,%2,%3};" \
        : "+f"((d)[0]), "+f"((d)[1]), "+f"((d)[2]), "+f"((d)[3]) \
        : "r"((a)[0]), "r"((a)[1]), "r"((a)[2]), "r"((a)[3]), \
          "r"((bf)[0]), "r"((bf)[1]))

#define CP16(dst, src) \
    asm volatile("cp.async.cg.shared.global [%0], [%1], 16;" :: "r"(dst), "l"(src) : "memory")
#define CP_COMMIT() asm volatile("cp.async.commit_group;" ::: "memory")
#define CP_WAIT0()  asm volatile("cp.async.wait_group 0;" ::: "memory")

// TF32 GEMM smem tile geometry: [buf][Ws 16x136][Xs 16x136] fp32
#define TROW 136
#define TTILE (16*TROW)          // u32 per array
#define TBUF  (2*TTILE)          // u32 per buffer

// ---------------------------------------------------------------------------
// K0: pre-round weights to tf32 (k-major).
// ---------------------------------------------------------------------------
__global__ __launch_bounds__(256) void cvt_w(
    const float* __restrict__ qw, const float* __restrict__ kvw,
    const float* __restrict__ pw)
{
    const int id = blockIdx.x * 256 + threadIdx.x;
    if (id < 256 * 640) {
        const int k = id / 640, oc = id % 640;
        const float v = (oc < 512) ? qw[oc * 256 + k] : kvw[(oc - 512) * 256 + k];
        g_wqt[id] = tf32r(v);
    } else {
        const int id2 = id - 256 * 640;
        if (id2 < 512 * 256) {
            const int k = id2 >> 8, oc = id2 & 255;
            g_wpt[id2] = tf32r(pw[(size_t)oc * 512 + k]);
        }
    }
}

// ---------------------------------------------------------------------------
// qkv epilogue pair store: (oc, pos even) + (oc, pos+1). Unchanged (proven).
// ---------------------------------------------------------------------------
__device__ __forceinline__ void store_pair(int b, int oc, int pos,
                                           float v0, float v1,
                                           const float* qb, const float* kvb)
{
    const int i = pos >> 10, s = pos & 1023, sp = s >> 1;
    if (oc < 512) {
        const float bias = qb[oc];
        uint32_t h, l;
        pack2(v0 + bias, v1 + bias, h, l);
        const size_t a = (size_t)((b*8 + (oc >> 6)) * 32 + i) * 32768 + (oc & 63) * 512 + sp;
        g_Qh[a] = h; g_Ql[a] = l;
    } else if (oc < 576) {
        const float bias = kvb[oc - 512];
        uint32_t h, l;
        pack2(v0 + bias, v1 + bias, h, l);
        const size_t a = (size_t)(b*32 + i) * 32768 + (oc - 512) * 512 + sp;
        g_Kh[a] = h; g_Kl[a] = l;
    } else {
        const float bias = kvb[oc - 512];
        const int cv = oc - 576;
        const int hh = s >> 5, w0 = s & 31;
        const int sigbase = ((hh >> 3) << 5) | ((hh & 7) << 2);
        const unsigned vb = ((unsigned)(b * 32 + i)) << 16;
        const int e20 = ((w0 & 7) << 6) | cv;
        const int e21 = (((w0 + 1) & 7) << 6) | cv;
        g_V[vb + (e20 << 7) + sigbase + (w0 >> 3)]       = v0 + bias;
        g_V[vb + (e21 << 7) + sigbase + ((w0 + 1) >> 3)] = v1 + bias;
    }
}

// ---------------------------------------------------------------------------
// TF32 GEMM compute step: W tile [16k][128oc], X tile [16k][128pos].
// Warp covers 64oc x 32pos (4 mb x 4 nb of m16n8). CVTB: round X frags.
// ---------------------------------------------------------------------------
template<bool CVTB>
__device__ __forceinline__ void gemm_step_t(
    const uint32_t* sm, int buf, int wm, int wn, int g, int t,
    float acc[4][4][4])
{
    const uint32_t* Ws = sm + buf * TBUF;
    const uint32_t* Xs = Ws + TTILE;
#pragma unroll
    for (int kk = 0; kk < 2; kk++) {
        const int r0 = kk * 8 + t, r1 = r0 + 4;
        uint32_t bf[4][2];
#pragma unroll
        for (int nb = 0; nb < 4; nb++) {
            const int n = wn * 32 + nb * 8 + g;
            bf[nb][0] = Xs[r0 * TROW + n];
            bf[nb][1] = Xs[r1 * TROW + n];
            if (CVTB) {
                bf[nb][0] = tf32r_u(bf[nb][0]);
                bf[nb][1] = tf32r_u(bf[nb][1]);
            }
        }
#pragma unroll
        for (int mb = 0; mb < 4; mb++) {
            const int m = wm * 64 + mb * 16 + g;
            uint32_t a[4];
            a[0] = Ws[r0 * TROW + m];     a[1] = Ws[r0 * TROW + m + 8];
            a[2] = Ws[r1 * TROW + m];     a[3] = Ws[r1 * TROW + m + 8];
#pragma unroll
            for (int nb = 0; nb < 4; nb++)
                MMAT(acc[mb][nb], a, bf[nb]);
        }
    }
}

// ---------------------------------------------------------------------------
// K1: QKV GEMM (TF32). grid(5 mc, 256 p-tiles, 2 b), 256 thr, double-buffer.
// ---------------------------------------------------------------------------
__global__ __launch_bounds__(256) void qkv_mma(
    const float* __restrict__ x,
    const float* __restrict__ qb, const float* __restrict__ kvb)
{
    __shared__ uint32_t sm[2 * TBUF];
    const int tid = threadIdx.x, lane = tid & 31, wid = tid >> 5;
    const int wm = wid & 1, wn = wid >> 1;
    const int g = lane >> 2, t = lane & 3;
    const int mc = blockIdx.x, p0 = blockIdx.y * 128, b = blockIdx.z;
    const uint32_t sbase = smem_u32(sm);

    const int r = tid >> 4, c8 = (tid & 15) * 8;

#define QKV_PF(s, buf) { \
    const int k_ = (s) * 16 + r; \
    const uint32_t d_ = sbase + ((buf) * TBUF + r * TROW + c8) * 4; \
    CP16(d_,                 &g_wqt[k_ * 640 + mc * 128 + c8]); \
    CP16(d_ + 16,            &g_wqt[k_ * 640 + mc * 128 + c8 + 4]); \
    CP16(d_ + TTILE * 4,     &x[((size_t)(b * 256 + k_) << 15) + p0 + c8]); \
    CP16(d_ + TTILE * 4 + 16,&x[((size_t)(b * 256 + k_) << 15) + p0 + c8 + 4]); \
    CP_COMMIT(); }

    float acc[4][4][4];
#pragma unroll
    for (int mb = 0; mb < 4; mb++)
#pragma unroll
        for (int nb = 0; nb < 4; nb++)
#pragma unroll
            for (int q = 0; q < 4; q++) acc[mb][nb][q] = 0.f;

    QKV_PF(0, 0);
    for (int s = 0; s < 16; s++) {
        CP_WAIT0();
        __syncthreads();
        if (s < 15) QKV_PF(s + 1, (s + 1) & 1);
        gemm_step_t<true>(sm, s & 1, wm, wn, g, t, acc);
    }
#undef QKV_PF

#pragma unroll
    for (int mb = 0; mb < 4; mb++) {
        const int oc_a = mc * 128 + wm * 64 + mb * 16 + g;
#pragma unroll
        for (int nb = 0; nb < 4; nb++) {
            const int pos_a = p0 + wn * 32 + nb * 8 + t * 2;
            store_pair(b, oc_a,     pos_a, acc[mb][nb][0], acc[mb][nb][1], qb, kvb);
            store_pair(b, oc_a + 8, pos_a, acc[mb][nb][2], acc[mb][nb][3], qb, kvb);
        }
    }
}

// ---------------------------------------------------------------------------
// K4: proj GEMM (TF32). grid(2 mc, 256 p-tiles, 2 b). K=512, 32 steps.
// Both operands pre-rounded -> no in-loop cvt.
// ---------------------------------------------------------------------------
__global__ __launch_bounds__(256) void proj_mma(
    const float* __restrict__ pb, const float* __restrict__ ls,
    float* __restrict__ out)
{
    __shared__ uint32_t sm[2 * TBUF];
    const int tid = threadIdx.x, lane = tid & 31, wid = tid >> 5;
    const int wm = wid & 1, wn = wid >> 1;
    const int g = lane >> 2, t = lane & 3;
    const int mc = blockIdx.x, p0 = blockIdx.y * 128, b = blockIdx.z;
    const uint32_t sbase = smem_u32(sm);

    const int r = tid >> 4, c8 = (tid & 15) * 8;

#define PROJ_PF(s, buf) { \
    const int k_ = (s) * 16 + r; \
    const uint32_t d_ = sbase + ((buf) * TBUF + r * TROW + c8) * 4; \
    CP16(d_,                 &g_wpt[k_ * 256 + mc * 128 + c8]); \
    CP16(d_ + 16,            &g_wpt[k_ * 256 + mc * 128 + c8 + 4]); \
    CP16(d_ + TTILE * 4,     &g_Op[((size_t)(b * 512 + k_) << 15) + p0 + c8]); \
    CP16(d_ + TTILE * 4 + 16,&g_Op[((size_t)(b * 512 + k_) << 15) + p0 + c8 + 4]); \
    CP_COMMIT(); }

    float acc[4][4][4];
#pragma unroll
    for (int mb = 0; mb < 4; mb++)
#pragma unroll
        for (int nb = 0; nb < 4; nb++)
#pragma unroll
            for (int q = 0; q < 4; q++) acc[mb][nb][q] = 0.f;

    PROJ_PF(0, 0);
    for (int s = 0; s < 32; s++) {
        CP_WAIT0();
        __syncthreads();
        if (s < 31) PROJ_PF(s + 1, (s + 1) & 1);
        gemm_step_t<false>(sm, s & 1, wm, wn, g, t, acc);
    }
#undef PROJ_PF

#pragma unroll
    for (int mb = 0; mb < 4; mb++) {
        const int r0 = mc * 128 + wm * 64 + mb * 16 + g;
        const float b0 = pb[r0],     s0 = ls[r0];
        const float b1 = pb[r0 + 8], s1 = ls[r0 + 8];
#pragma unroll
        for (int nb = 0; nb < 4; nb++) {
            const int pos_a = p0 + wn * 32 + nb * 8 + t * 2;
            float* o0 = out + (((size_t)(b * 256 + r0)) << 15) + pos_a;
            float* o1 = out + (((size_t)(b * 256 + r0 + 8)) << 15) + pos_a;
            o0[0] = (acc[mb][nb][0] + b0) * s0;
            o0[1] = (acc[mb][nb][1] + b0) * s0;
            o1[0] = (acc[mb][nb][2] + b1) * s1;
            o1[1] = (acc[mb][nb][3] + b1) * s1;
        }
    }
}

// ---------------------------------------------------------------------------
// K2: scores via bf16 MMA (unchanged, proven). grid(64 fchunks, 16 bn).
// ---------------------------------------------------------------------------
#define SROW 36
__global__ __launch_bounds__(128) void scores_mma()
{
    __shared__ uint32_t sm[2 * 4 * 32 * SROW];
    const int tid = threadIdx.x, lane = tid & 31, w = tid >> 5;
    const int g = lane >> 2, t = lane & 3;
    const int fc = blockIdx.x, bn = blockIdx.y, b = bn >> 3;
    const uint32_t sbase = smem_u32(sm);

    const int r = tid >> 2, q = tid & 3;
    const size_t qrow = ((size_t)(bn * 32 + r)) * 32768 + fc * 512 + q * 8;
    const size_t krow = ((size_t)(b  * 32 + r)) * 32768 + fc * 512 + q * 8;
    const uint32_t dst0 = sbase + (r * SROW + q * 8) * 4;
    const uint32_t A1 = 32 * SROW * 4;

    float acc[2][4][4];
#pragma unroll
    for (int mi = 0; mi < 2; mi++)
#pragma unroll
        for (int ni = 0; ni < 4; ni++)
#pragma unroll
            for (int z = 0; z < 4; z++) acc[mi][ni][z] = 0.f;

    {
        CP16(dst0,        &g_Qh[qrow]);     CP16(dst0 + 16,        &g_Qh[qrow + 4]);
        CP16(dst0 + A1,   &g_Ql[qrow]);     CP16(dst0 + A1 + 16,   &g_Ql[qrow + 4]);
        CP16(dst0 + 2*A1, &g_Kh[krow]);     CP16(dst0 + 2*A1 + 16, &g_Kh[krow + 4]);
        CP16(dst0 + 3*A1, &g_Kl[krow]);     CP16(dst0 + 3*A1 + 16, &g_Kl[krow + 4]);
        CP_COMMIT();
    }

    for (int tl = 0; tl < 16; tl++) {
        CP_WAIT0();
        __syncthreads();
        if (tl < 15) {
            const uint32_t d = dst0 + ((tl + 1) & 1) * (4 * A1);
            const size_t qo = qrow + (tl + 1) * 32, ko = krow + (tl + 1) * 32;
            CP16(d,        &g_Qh[qo]);     CP16(d + 16,        &g_Qh[qo + 4]);
            CP16(d + A1,   &g_Ql[qo]);     CP16(d + A1 + 16,   &g_Ql[qo + 4]);
            CP16(d + 2*A1, &g_Kh[ko]);     CP16(d + 2*A1 + 16, &g_Kh[ko + 4]);
            CP16(d + 3*A1, &g_Kl[ko]);     CP16(d + 3*A1 + 16, &g_Kl[ko + 4]);
            CP_COMMIT();
        }
        const uint32_t* Qh = sm + ((tl & 1) * 4 + 0) * 32 * SROW;
        const uint32_t* Ql = sm + ((tl & 1) * 4 + 1) * 32 * SROW;
        const uint32_t* Kh = sm + ((tl & 1) * 4 + 2) * 32 * SROW;
        const uint32_t* Kl = sm + ((tl & 1) * 4 + 3) * 32 * SROW;
        const int kp = w * 8;

        uint32_t bh[4][2], bl[4][2];
#pragma unroll
        for (int ni = 0; ni < 4; ni++) {
            const int col = ni * 8 + g;
            bh[ni][0] = Kh[col * SROW + kp + t];
            bh[ni][1] = Kh[col * SROW + kp + t + 4];
            bl[ni][0] = Kl[col * SROW + kp + t];
            bl[ni][1] = Kl[col * SROW + kp + t + 4];
        }
#pragma unroll
        for (int mi = 0; mi < 2; mi++) {
            const int row = mi * 16 + g;
            uint32_t ah[4], al_[4];
            ah[0]  = Qh[row * SROW + kp + t];       ah[1]  = Qh[(row + 8) * SROW + kp + t];
            ah[2]  = Qh[row * SROW + kp + t + 4];   ah[3]  = Qh[(row + 8) * SROW + kp + t + 4];
            al_[0] = Ql[row * SROW + kp + t];       al_[1] = Ql[(row + 8) * SROW + kp + t];
            al_[2] = Ql[row * SROW + kp + t + 4];   al_[3] = Ql[(row + 8) * SROW + kp + t + 4];
#pragma unroll
            for (int ni = 0; ni < 4; ni++) {
                MMA16816(acc[mi][ni], ah,  bh[ni]);
                MMA16816(acc[mi][ni], ah,  bl[ni]);
                MMA16816(acc[mi][ni], al_, bh[ni]);
            }
        }
    }

    __syncthreads();
    float* red = (float*)sm;
#pragma unroll
    for (int mi = 0; mi < 2; mi++)
#pragma unroll
        for (int ni = 0; ni < 4; ni++) {
            const int i0 = mi * 16 + g, j0 = ni * 8 + t * 2;
            red[w * 1024 + i0 * 32 + j0]           = acc[mi][ni][0];
            red[w * 1024 + i0 * 32 + j0 + 1]       = acc[mi][ni][1];
            red[w * 1024 + (i0 + 8) * 32 + j0]     = acc[mi][ni][2];
            red[w * 1024 + (i0 + 8) * 32 + j0 + 1] = acc[mi][ni][3];
        }
    __syncthreads();
    const unsigned abase = (unsigned)(fc * 16 + bn) * 1024u;
#pragma unroll
    for (int e = 0; e < 8; e++) {
        const int idx = tid * 8 + e;
        g_Ap[abase + idx] = red[idx] + red[1024 + idx] + red[2048 + idx] + red[3072 + idx];
    }
}

// ---------------------------------------------------------------------------
__global__ __launch_bounds__(1024) void softmax_kernel()
{
    const int bn = blockIdx.x;
    const int tid = threadIdx.x;
    const int i = tid >> 5, j = tid & 31;
    float v = 0.f;
#pragma unroll
    for (int c = 0; c < 64; c++)
        v += g_Ap[((unsigned)(c * 16 + bn) << 10) + (i << 5) + j];
    v *= 0.125f;
    float m = v;
#pragma unroll
    for (int o = 16; o; o >>= 1) m = fmaxf(m, __shfl_xor_sync(0xffffffffu, m, o));
    float e = expf(v - m);
    float s = e;
#pragma unroll
    for (int o = 16; o; o >>= 1) s += __shfl_xor_sync(0xffffffffu, s, o);
    g_A[((unsigned)bn << 10) + (i << 5) + j] = e / s;
}

// ---------------------------------------------------------------------------
// K3: O' = A @ V'. No V smem (per-thread columns), direct tf32-rounded
// coalesced stores into g_Op fp32 — no in-loop syncs.
// ---------------------------------------------------------------------------
__global__ __launch_bounds__(256, 2) void av_kernel()
{
    __shared__ __align__(16) float As[1024];
    const int tid = threadIdx.x;
    const int bn = blockIdx.y;
    const int b = bn >> 3, n = bn & 7;
    const int e0 = blockIdx.x * 16;

#pragma unroll
    for (int l = 0; l < 4; l++)
        As[l * 256 + tid] = g_A[((unsigned)bn << 10) + l * 256 + tid];
    __syncthreads();

    const int eh  = tid >> 7;
    const int sig = tid & 127;
    const unsigned vbase = ((unsigned)(b * 32)) << 16;

    for (int ei = 0; ei < 16; ei += 2) {
        const int e = e0 + ei + eh;
        float v[32];
#pragma unroll
        for (int j = 0; j < 32; j++)
            v[j] = g_V[vbase + ((unsigned)j << 16) + (e << 7) + sig];

        const size_t obase = ((size_t)(b * 512 + e) << 15) + (n << 7) + sig;
#pragma unroll
        for (int half = 0; half < 2; half++) {
            float acc[16];
#pragma unroll
            for (int i = 0; i < 16; i++) acc[i] = 0.f;
#pragma unroll
            for (int i = 0; i < 16; i++) {
                const int ig = half * 16 + i;
#pragma unroll
                for (int j4 = 0; j4 < 8; j4++) {
                    const float4 a = *(const float4*)&As[(ig << 5) + j4 * 4];
                    acc[i] += a.x * v[j4*4] + a.y * v[j4*4+1]
                            + a.z * v[j4*4+2] + a.w * v[j4*4+3];
                }
            }
#pragma unroll
            for (int i = 0; i < 16; i++)
                g_Op[obase + ((size_t)(half * 16 + i) << 10)] = tf32r(acc[i]);
        }
    }
}

// ---------------------------------------------------------------------------
extern "C" void kernel_launch(void* const* d_in, const int* in_sizes, int n_in,
                              void* d_out, int out_size)
{
    (void)in_sizes; (void)n_in; (void)out_size;
    const float* x   = (const float*)d_in[0];
    const float* qw  = (const float*)d_in[1];
    const float* qb  = (const float*)d_in[2];
    const float* kvw = (const float*)d_in[3];
    const float* kvb = (const float*)d_in[4];
    const float* pw  = (const float*)d_in[5];
    const float* pb  = (const float*)d_in[6];
    const float* ls  = (const float*)d_in[7];
    float* out = (float*)d_out;

    cvt_w         <<<1152, 256>>>(qw, kvw, pw);
    qkv_mma       <<<dim3(5, 256, 2), 256>>>(x, qb, kvb);
    scores_mma    <<<dim3(64, 16), 128>>>();
    softmax_kernel<<<16, 1024>>>();
    av_kernel     <<<dim3(32, 16), 256>>>();
    proj_mma      <<<dim3(2, 256, 2), 256>>>(pb, ls, out);
}

// round 17
// speedup vs baseline: 2.5627x; 2.5627x over previous
#include <cuda_runtime.h>
#include <cuda_bf16.h>
#include <cuda_fp16.h>
#include <cstdint>

// ---------------------------------------------------------------------------
// MobileAttention3D: B=2, C=256, D=32, H=W=32, NH=8, KD=VD=64
//
// R15 = R13 (530us) + proj GEMM on fp16 2-term (X=Xh+Xl fp16 exact-split,
//        W single rounded fp16; error linear ~2.3e-4, no softmax amplif.)
//      + av: V smem staging removed (direct reg loads).
// qkv/scores keep the proven 3-term bf16 truncation split.
// ---------------------------------------------------------------------------

#define NPOS 32768

__device__ float    g_V  [2*32*65536];    // [b][j][e][sigma] (shuffled)
__device__ float    g_Ap [64*16*1024];    // partial logits [fc][bn][i*32+j]
__device__ float    g_A  [16*1024];       // softmaxed attn
__device__ uint32_t g_oph[2*256*32768];   // proj-input fp16-hi pairs [b][ep][p']
__device__ uint32_t g_opl[2*256*32768];   // proj-input fp16-lo pairs
__device__ uint32_t g_wqh[128*640];       // qkv W bf16 hi pairs [kp][oc]
__device__ uint32_t g_wql[128*640];
__device__ uint32_t g_wp2[256*256];       // proj W fp16 pairs [kp][oc]
__device__ uint32_t g_xph[2*128*32768];   // x bf16-hi pairs [b][cp][p]
__device__ uint32_t g_xpl[2*128*32768];
__device__ uint32_t g_Qh [2*8*32*32768];  // Q bf16 hi pairs [(bn*32+i)][fp]
__device__ uint32_t g_Ql [2*8*32*32768];
__device__ uint32_t g_Kh [2*32*32768];    // K bf16 hi pairs [(b*32+j)][fp]
__device__ uint32_t g_Kl [2*32*32768];

// ---- helpers ----
// bf16 truncation split (proven): hi = top16 bits, lo = x - hi (exact), PRMT.
__device__ __forceinline__ void pack2(float a, float b, uint32_t& hi, uint32_t& lo) {
    const uint32_t au = __float_as_uint(a), bu = __float_as_uint(b);
    const float ah = __uint_as_float(au & 0xFFFF0000u);
    const float bh = __uint_as_float(bu & 0xFFFF0000u);
    hi = __byte_perm(au, bu, 0x7632);
    lo = __byte_perm(__float_as_uint(a - ah), __float_as_uint(b - bh), 0x7632);
}
// fp16 exact 2-term split of values (hi = rn fp16, lo = residual in fp16).
__device__ __forceinline__ void pack2h(float a, float b, uint32_t& hi, uint32_t& lo) {
    const __half ah = __float2half_rn(a), bh = __float2half_rn(b);
    const __half al = __float2half_rn(a - __half2float(ah));
    const __half bl = __float2half_rn(b - __half2float(bh));
    hi = (uint32_t)__half_as_ushort(ah) | ((uint32_t)__half_as_ushort(bh) << 16);
    lo = (uint32_t)__half_as_ushort(al) | ((uint32_t)__half_as_ushort(bl) << 16);
}
__device__ __forceinline__ uint32_t smem_u32(const void* p) {
    uint32_t a;
    asm("{ .reg .u64 t; cvta.to.shared.u64 t, %1; cvt.u32.u64 %0, t; }" : "=r"(a) : "l"(p));
    return a;
}

#define MMA16816(d, a, bf) \
    asm volatile("mma.sync.aligned.m16n8k16.row.col.f32.bf16.bf16.f32 " \
        "{%0,%1,%2,%3}, {%4,%5,%6,%7}, {%8,%9}, {%0,%1,%2,%3};" \
        : "+f"((d)[0]), "+f"((d)[1]), "+f"((d)[2]), "+f"((d)[3]) \
        : "r"((a)[0]), "r"((a)[1]), "r"((a)[2]), "r"((a)[3]), \
          "r"((bf)[0]), "r"((bf)[1]))

#define MMAH(d, a, bf) \
    asm volatile("mma.sync.aligned.m16n8k16.row.col.f32.f16.f16.f32 " \
        "{%0,%1,%2,%3}, {%4,%5,%6,%7}, {%8,%9}, {%0,%1,%2,%3};" \
        : "+f"((d)[0]), "+f"((d)[1]), "+f"((d)[2]), "+f"((d)[3]) \
        : "r"((a)[0]), "r"((a)[1]), "r"((a)[2]), "r"((a)[3]), \
          "r"((bf)[0]), "r"((bf)[1]))

#define CP16(dst, src) \
    asm volatile("cp.async.cg.shared.global [%0], [%1], 16;" :: "r"(dst), "l"(src) : "memory")
#define CP_COMMIT() asm volatile("cp.async.commit_group;" ::: "memory")
#define CP_WAIT0()  asm volatile("cp.async.wait_group 0;" ::: "memory")
#define CP_WAIT1()  asm volatile("cp.async.wait_group 1;" ::: "memory")

#define ROWW 136
#define AOFF (8*ROWW*4)             // bytes per array within a buffer
#define QBUFB (4*AOFF)              // qkv: 4 arrays per buffer
#define SMEM_3BUF (3*QBUFB)         // 52224 bytes (qkv triple buffer)
#define PTILE (8*ROWW)              // u32 per proj array
#define PBUFU (3*PTILE)             // u32 per proj buffer (W, Xh, Xl)

// ---------------------------------------------------------------------------
// K0a: convert x to packed bf16 hi/lo pairs over adjacent channels.
// ---------------------------------------------------------------------------
__global__ __launch_bounds__(256) void cvt_x(const float* __restrict__ x)
{
    const int p  = blockIdx.x * 1024 + threadIdx.x * 4;
    const int cp = blockIdx.y;
    const int b  = blockIdx.z;
    const float4 x0 = *(const float4*)&x[((size_t)(b * 256 + 2*cp    ) << 15) + p];
    const float4 x1 = *(const float4*)&x[((size_t)(b * 256 + 2*cp + 1) << 15) + p];
    uint4 h, l;
    pack2(x0.x, x1.x, h.x, l.x);
    pack2(x0.y, x1.y, h.y, l.y);
    pack2(x0.z, x1.z, h.z, l.z);
    pack2(x0.w, x1.w, h.w, l.w);
    const size_t o = ((size_t)(b * 128 + cp) << 15) + p;
    *(uint4*)&g_xph[o] = h;
    *(uint4*)&g_xpl[o] = l;
}

// ---------------------------------------------------------------------------
// K0b: pre-pack weights. qkv: bf16 hi/lo pairs; proj: single fp16 pairs.
// ---------------------------------------------------------------------------
__global__ __launch_bounds__(256) void pack_w(
    const float* __restrict__ qw, const float* __restrict__ kvw,
    const float* __restrict__ pw)
{
    const int id = blockIdx.x * 256 + threadIdx.x;
    if (id < 128 * 640) {
        const int kp = id / 640, oc = id % 640;
        const float* wr = (oc < 512) ? qw + (size_t)oc * 256
                                     : kvw + (size_t)(oc - 512) * 256;
        uint32_t h, l;
        pack2(wr[2*kp], wr[2*kp + 1], h, l);
        g_wqh[id] = h; g_wql[id] = l;
    } else {
        const int id2 = id - 128 * 640;
        if (id2 < 256 * 256) {
            const int kp = id2 >> 8, oc = id2 & 255;
            const float w0 = pw[(size_t)oc * 512 + 2*kp];
            const float w1 = pw[(size_t)oc * 512 + 2*kp + 1];
            const __half h0 = __float2half_rn(w0), h1 = __float2half_rn(w1);
            g_wp2[id2] = (uint32_t)__half_as_ushort(h0)
                       | ((uint32_t)__half_as_ushort(h1) << 16);
        }
    }
}

// ---------------------------------------------------------------------------
// qkv epilogue pair store (unchanged, proven).
// ---------------------------------------------------------------------------
__device__ __forceinline__ void store_pair(int b, int oc, int pos,
                                           float v0, float v1,
                                           const float* qb, const float* kvb)
{
    const int i = pos >> 10, s = pos & 1023, sp = s >> 1;
    if (oc < 512) {
        const float bias = qb[oc];
        uint32_t h, l;
        pack2(v0 + bias, v1 + bias, h, l);
        const size_t a = (size_t)((b*8 + (oc >> 6)) * 32 + i) * 32768 + (oc & 63) * 512 + sp;
        g_Qh[a] = h; g_Ql[a] = l;
    } else if (oc < 576) {
        const float bias = kvb[oc - 512];
        uint32_t h, l;
        pack2(v0 + bias, v1 + bias, h, l);
        const size_t a = (size_t)(b*32 + i) * 32768 + (oc - 512) * 512 + sp;
        g_Kh[a] = h; g_Kl[a] = l;
    } else {
        const float bias = kvb[oc - 512];
        const int cv = oc - 576;
        const int hh = s >> 5, w0 = s & 31;
        const int sigbase = ((hh >> 3) << 5) | ((hh & 7) << 2);
        const unsigned vb = ((unsigned)(b * 32 + i)) << 16;
        const int e20 = ((w0 & 7) << 6) | cv;
        const int e21 = (((w0 + 1) & 7) << 6) | cv;
        g_V[vb + (e20 << 7) + sigbase + (w0 >> 3)]       = v0 + bias;
        g_V[vb + (e21 << 7) + sigbase + ((w0 + 1) >> 3)] = v1 + bias;
    }
}

// ---------------------------------------------------------------------------
// bf16 3-term GEMM compute step (qkv; unchanged, proven).
// ---------------------------------------------------------------------------
__device__ __forceinline__ void gemm_step(
    const uint32_t* sm, int buf, int wm, int wn, int g, int t,
    float acc[4][4][4])
{
    const uint32_t* Awh = sm + (buf * 4 + 0) * 8 * ROWW;
    const uint32_t* Awl = sm + (buf * 4 + 1) * 8 * ROWW;
    const uint32_t* Bxh = sm + (buf * 4 + 2) * 8 * ROWW;
    const uint32_t* Bxl = sm + (buf * 4 + 3) * 8 * ROWW;

    uint32_t bh[4][2], bl[4][2];
#pragma unroll
    for (int nb = 0; nb < 4; nb++) {
        const int nbase = wn * 32 + nb * 8 + g;
        bh[nb][0] = Bxh[t * ROWW + nbase];       bh[nb][1] = Bxh[(t+4) * ROWW + nbase];
        bl[nb][0] = Bxl[t * ROWW + nbase];       bl[nb][1] = Bxl[(t+4) * ROWW + nbase];
    }
#pragma unroll
    for (int mb = 0; mb < 4; mb++) {
        const int mbase = wm * 64 + mb * 16 + g;
        uint32_t ah[4], al_[4];
        ah[0]  = Awh[t * ROWW + mbase];     ah[1]  = Awh[t * ROWW + mbase + 8];
        ah[2]  = Awh[(t+4) * ROWW + mbase]; ah[3]  = Awh[(t+4) * ROWW + mbase + 8];
        al_[0] = Awl[t * ROWW + mbase];     al_[1] = Awl[t * ROWW + mbase + 8];
        al_[2] = Awl[(t+4) * ROWW + mbase]; al_[3] = Awl[(t+4) * ROWW + mbase + 8];
#pragma unroll
        for (int nb = 0; nb < 4; nb++) {
            MMA16816(acc[mb][nb], ah,  bh[nb]);
            MMA16816(acc[mb][nb], ah,  bl[nb]);
            MMA16816(acc[mb][nb], al_, bh[nb]);
        }
    }
}

// ---------------------------------------------------------------------------
// K1: QKV GEMM. grid(5 mc, 256 p-tiles, 2 b). Triple-buffered (R13 verbatim).
// ---------------------------------------------------------------------------
__global__ __launch_bounds__(256) void qkv_mma(
    const float* __restrict__ qb, const float* __restrict__ kvb)
{
    extern __shared__ uint32_t dsm[];
    const int tid = threadIdx.x, lane = tid & 31, wid = tid >> 5;
    const int wm = wid & 1, wn = wid >> 1;
    const int g = lane >> 2, t = lane & 3;
    const int mc = blockIdx.x, p0 = blockIdx.y * 128, b = blockIdx.z;
    const uint32_t sbase = smem_u32(dsm);

    const int r = tid >> 5, c4 = (tid & 31) * 4;
    const uint32_t dst0 = sbase + (r * ROWW + c4) * 4;

#define QKV_PF(s, d) { \
    const int sr_ = (s) * 8 + r; \
    const int wi_ = sr_ * 640 + mc * 128 + c4; \
    const size_t xi_ = ((size_t)(b * 128 + sr_) << 15) + p0 + c4; \
    CP16((d),          &g_wqh[wi_]); \
    CP16((d) + AOFF,   &g_wql[wi_]); \
    CP16((d) + 2*AOFF, &g_xph[xi_]); \
    CP16((d) + 3*AOFF, &g_xpl[xi_]); \
    CP_COMMIT(); }

    float acc[4][4][4];
#pragma unroll
    for (int mb = 0; mb < 4; mb++)
#pragma unroll
        for (int nb = 0; nb < 4; nb++)
#pragma unroll
            for (int q = 0; q < 4; q++) acc[mb][nb][q] = 0.f;

    QKV_PF(0, dst0);
    QKV_PF(1, dst0 + QBUFB);

    for (int s = 0; s < 16; s++) {
        CP_WAIT1();
        __syncthreads();
        if (s + 2 < 16) {
            QKV_PF(s + 2, dst0 + ((s + 2) % 3) * QBUFB);
        } else {
            CP_COMMIT();
        }
        gemm_step(dsm, s % 3, wm, wn, g, t, acc);
    }

#pragma unroll
    for (int mb = 0; mb < 4; mb++) {
        const int oc_a = mc * 128 + wm * 64 + mb * 16 + g;
#pragma unroll
        for (int nb = 0; nb < 4; nb++) {
            const int pos_a = p0 + wn * 32 + nb * 8 + t * 2;
            store_pair(b, oc_a,     pos_a, acc[mb][nb][0], acc[mb][nb][1], qb, kvb);
            store_pair(b, oc_a + 8, pos_a, acc[mb][nb][2], acc[mb][nb][3], qb, kvb);
        }
    }
#undef QKV_PF
}

// ---------------------------------------------------------------------------
// K4: proj GEMM (fp16 2-term). grid(2 mc, 256 p-tiles, 2 b), 256 thr.
// D = W_fp16 · (Xh + Xl): 2 MMAs per tile, 32 MMA + 32 LDS per step.
// ---------------------------------------------------------------------------
__global__ __launch_bounds__(256) void proj_mma(
    const float* __restrict__ pb, const float* __restrict__ ls,
    float* __restrict__ out)
{
    __shared__ uint32_t sm[2 * PBUFU];   // 26112 B
    const int tid = threadIdx.x, lane = tid & 31, wid = tid >> 5;
    const int wm = wid & 1, wn = wid >> 1;
    const int g = lane >> 2, t = lane & 3;
    const int mc = blockIdx.x, p0 = blockIdx.y * 128, b = blockIdx.z;
    const uint32_t sbase = smem_u32(sm);

    const int r = tid >> 5, c4 = (tid & 31) * 4;

#define PROJ_PF(s, buf) { \
    const int kp_ = (s) * 8 + r; \
    const uint32_t d_ = sbase + ((buf) * PBUFU + r * ROWW + c4) * 4; \
    const size_t xi_ = ((size_t)(b * 256 + kp_) << 15) + p0 + c4; \
    CP16(d_,               &g_wp2[kp_ * 256 + mc * 128 + c4]); \
    CP16(d_ + PTILE * 4,   &g_oph[xi_]); \
    CP16(d_ + 2*PTILE * 4, &g_opl[xi_]); \
    CP_COMMIT(); }

    float acc[4][4][4];
#pragma unroll
    for (int mb = 0; mb < 4; mb++)
#pragma unroll
        for (int nb = 0; nb < 4; nb++)
#pragma unroll
            for (int q = 0; q < 4; q++) acc[mb][nb][q] = 0.f;

    PROJ_PF(0, 0);
    for (int s = 0; s < 32; s++) {
        CP_WAIT0();
        __syncthreads();
        if (s < 31) PROJ_PF(s + 1, (s + 1) & 1);
        // compute on buffer s&1
        const uint32_t* Wf = sm + (s & 1) * PBUFU;
        const uint32_t* Xh = Wf + PTILE;
        const uint32_t* Xl = Xh + PTILE;

        uint32_t bh[4][2], bl[4][2];
#pragma unroll
        for (int nb = 0; nb < 4; nb++) {
            const int nbase = wn * 32 + nb * 8 + g;
            bh[nb][0] = Xh[t * ROWW + nbase];   bh[nb][1] = Xh[(t+4) * ROWW + nbase];
            bl[nb][0] = Xl[t * ROWW + nbase];   bl[nb][1] = Xl[(t+4) * ROWW + nbase];
        }
#pragma unroll
        for (int mb = 0; mb < 4; mb++) {
            const int mbase = wm * 64 + mb * 16 + g;
            uint32_t a[4];
            a[0] = Wf[t * ROWW + mbase];     a[1] = Wf[t * ROWW + mbase + 8];
            a[2] = Wf[(t+4) * ROWW + mbase]; a[3] = Wf[(t+4) * ROWW + mbase + 8];
#pragma unroll
            for (int nb = 0; nb < 4; nb++) {
                MMAH(acc[mb][nb], a, bh[nb]);
                MMAH(acc[mb][nb], a, bl[nb]);
            }
        }
    }
#undef PROJ_PF

#pragma unroll
    for (int mb = 0; mb < 4; mb++) {
        const int r0 = mc * 128 + wm * 64 + mb * 16 + g;
        const float b0 = pb[r0],     s0 = ls[r0];
        const float b1 = pb[r0 + 8], s1 = ls[r0 + 8];
#pragma unroll
        for (int nb = 0; nb < 4; nb++) {
            const int pos_a = p0 + wn * 32 + nb * 8 + t * 2;
            float* o0 = out + (((size_t)(b * 256 + r0)) << 15) + pos_a;
            float* o1 = out + (((size_t)(b * 256 + r0 + 8)) << 15) + pos_a;
            o0[0] = (acc[mb][nb][0] + b0) * s0;
            o0[1] = (acc[mb][nb][1] + b0) * s0;
            o1[0] = (acc[mb][nb][2] + b1) * s1;
            o1[1] = (acc[mb][nb][3] + b1) * s1;
        }
    }
}

// ---------------------------------------------------------------------------
// K2: scores via bf16 MMA (unchanged, proven). grid(64 fchunks, 16 bn).
// ---------------------------------------------------------------------------
#define SROW 36
__global__ __launch_bounds__(128) void scores_mma()
{
    __shared__ uint32_t sm[2 * 4 * 32 * SROW];
    const int tid = threadIdx.x, lane = tid & 31, w = tid >> 5;
    const int g = lane >> 2, t = lane & 3;
    const int fc = blockIdx.x, bn = blockIdx.y, b = bn >> 3;
    const uint32_t sbase = smem_u32(sm);

    const int r = tid >> 2, q = tid & 3;
    const size_t qrow = ((size_t)(bn * 32 + r)) * 32768 + fc * 512 + q * 8;
    const size_t krow = ((size_t)(b  * 32 + r)) * 32768 + fc * 512 + q * 8;
    const uint32_t dst0 = sbase + (r * SROW + q * 8) * 4;
    const uint32_t A1 = 32 * SROW * 4;

    float acc[2][4][4];
#pragma unroll
    for (int mi = 0; mi < 2; mi++)
#pragma unroll
        for (int ni = 0; ni < 4; ni++)
#pragma unroll
            for (int z = 0; z < 4; z++) acc[mi][ni][z] = 0.f;

    {
        CP16(dst0,        &g_Qh[qrow]);     CP16(dst0 + 16,        &g_Qh[qrow + 4]);
        CP16(dst0 + A1,   &g_Ql[qrow]);     CP16(dst0 + A1 + 16,   &g_Ql[qrow + 4]);
        CP16(dst0 + 2*A1, &g_Kh[krow]);     CP16(dst0 + 2*A1 + 16, &g_Kh[krow + 4]);
        CP16(dst0 + 3*A1, &g_Kl[krow]);     CP16(dst0 + 3*A1 + 16, &g_Kl[krow + 4]);
        CP_COMMIT();
    }

    for (int tl = 0; tl < 16; tl++) {
        CP_WAIT0();
        __syncthreads();
        if (tl < 15) {
            const uint32_t d = dst0 + ((tl + 1) & 1) * (4 * A1);
            const size_t qo = qrow + (tl + 1) * 32, ko = krow + (tl + 1) * 32;
            CP16(d,        &g_Qh[qo]);     CP16(d + 16,        &g_Qh[qo + 4]);
            CP16(d + A1,   &g_Ql[qo]);     CP16(d + A1 + 16,   &g_Ql[qo + 4]);
            CP16(d + 2*A1, &g_Kh[ko]);     CP16(d + 2*A1 + 16, &g_Kh[ko + 4]);
            CP16(d + 3*A1, &g_Kl[ko]);     CP16(d + 3*A1 + 16, &g_Kl[ko + 4]);
            CP_COMMIT();
        }
        const uint32_t* Qh = sm + ((tl & 1) * 4 + 0) * 32 * SROW;
        const uint32_t* Ql = sm + ((tl & 1) * 4 + 1) * 32 * SROW;
        const uint32_t* Kh = sm + ((tl & 1) * 4 + 2) * 32 * SROW;
        const uint32_t* Kl = sm + ((tl & 1) * 4 + 3) * 32 * SROW;
        const int kp = w * 8;

        uint32_t bh[4][2], bl[4][2];
#pragma unroll
        for (int ni = 0; ni < 4; ni++) {
            const int col = ni * 8 + g;
            bh[ni][0] = Kh[col * SROW + kp + t];
            bh[ni][1] = Kh[col * SROW + kp + t + 4];
            bl[ni][0] = Kl[col * SROW + kp + t];
            bl[ni][1] = Kl[col * SROW + kp + t + 4];
        }
#pragma unroll
        for (int mi = 0; mi < 2; mi++) {
            const int row = mi * 16 + g;
            uint32_t ah[4], al_[4];
            ah[0]  = Qh[row * SROW + kp + t];       ah[1]  = Qh[(row + 8) * SROW + kp + t];
            ah[2]  = Qh[row * SROW + kp + t + 4];   ah[3]  = Qh[(row + 8) * SROW + kp + t + 4];
            al_[0] = Ql[row * SROW + kp + t];       al_[1] = Ql[(row + 8) * SROW + kp + t];
            al_[2] = Ql[row * SROW + kp + t + 4];   al_[3] = Ql[(row + 8) * SROW + kp + t + 4];
#pragma unroll
            for (int ni = 0; ni < 4; ni++) {
                MMA16816(acc[mi][ni], ah,  bh[ni]);
                MMA16816(acc[mi][ni], ah,  bl[ni]);
                MMA16816(acc[mi][ni], al_, bh[ni]);
            }
        }
    }

    __syncthreads();
    float* red = (float*)sm;
#pragma unroll
    for (int mi = 0; mi < 2; mi++)
#pragma unroll
        for (int ni = 0; ni < 4; ni++) {
            const int i0 = mi * 16 + g, j0 = ni * 8 + t * 2;
            red[w * 1024 + i0 * 32 + j0]           = acc[mi][ni][0];
            red[w * 1024 + i0 * 32 + j0 + 1]       = acc[mi][ni][1];
            red[w * 1024 + (i0 + 8) * 32 + j0]     = acc[mi][ni][2];
            red[w * 1024 + (i0 + 8) * 32 + j0 + 1] = acc[mi][ni][3];
        }
    __syncthreads();
    const unsigned abase = (unsigned)(fc * 16 + bn) * 1024u;
#pragma unroll
    for (int e = 0; e < 8; e++) {
        const int idx = tid * 8 + e;
        g_Ap[abase + idx] = red[idx] + red[1024 + idx] + red[2048 + idx] + red[3072 + idx];
    }
}

// ---------------------------------------------------------------------------
__global__ __launch_bounds__(1024) void softmax_kernel()
{
    const int bn = blockIdx.x;
    const int tid = threadIdx.x;
    const int i = tid >> 5, j = tid & 31;
    float v = 0.f;
#pragma unroll
    for (int c = 0; c < 64; c++)
        v += g_Ap[((unsigned)(c * 16 + bn) << 10) + (i << 5) + j];
    v *= 0.125f;
    float m = v;
#pragma unroll
    for (int o = 16; o; o >>= 1) m = fmaxf(m, __shfl_xor_sync(0xffffffffu, m, o));
    float e = expf(v - m);
    float s = e;
#pragma unroll
    for (int o = 16; o; o >>= 1) s += __shfl_xor_sync(0xffffffffu, s, o);
    g_A[((unsigned)bn << 10) + (i << 5) + j] = e / s;
}

// ---------------------------------------------------------------------------
// K3: O' = A @ V'. Direct V reg loads (no staging), fp16 pair output.
// ---------------------------------------------------------------------------
__global__ __launch_bounds__(256, 2) void av_kernel()
{
    __shared__ __align__(16) float As[1024];
    __shared__ float Xc[2][32][128];     // acc exchange between eh halves
    const int tid = threadIdx.x;
    const int bn = blockIdx.y;
    const int b = bn >> 3, n = bn & 7;
    const int e0 = blockIdx.x * 16;

#pragma unroll
    for (int l = 0; l < 4; l++)
        As[l * 256 + tid] = g_A[((unsigned)bn << 10) + l * 256 + tid];
    __syncthreads();

    const int eh  = tid >> 7;
    const int sig = tid & 127;
    const unsigned vbase = ((unsigned)(b * 32)) << 16;

    for (int ei = 0; ei < 16; ei += 2) {
        const int e = e0 + ei + eh;
        float v[32];
#pragma unroll
        for (int j = 0; j < 32; j++)
            v[j] = g_V[vbase + ((unsigned)j << 16) + (e << 7) + sig];

#pragma unroll
        for (int half = 0; half < 2; half++) {
            float acc[16];
#pragma unroll
            for (int i = 0; i < 16; i++) acc[i] = 0.f;
#pragma unroll
            for (int i = 0; i < 16; i++) {
                const int ig = half * 16 + i;
#pragma unroll
                for (int j4 = 0; j4 < 8; j4++) {
                    const float4 a = *(const float4*)&As[(ig << 5) + j4 * 4];
                    acc[i] += a.x * v[j4*4] + a.y * v[j4*4+1]
                            + a.z * v[j4*4+2] + a.w * v[j4*4+3];
                }
            }
#pragma unroll
            for (int i = 0; i < 16; i++)
                Xc[eh][half * 16 + i][sig] = acc[i];
        }
        __syncthreads();

        const int ep = (e0 + ei) >> 1;
        const size_t obase = ((size_t)(b * 256 + ep) << 15) + (n << 7) + sig;
#pragma unroll
        for (int ii = 0; ii < 16; ii++) {
            const int i = eh * 16 + ii;
            uint32_t h, l;
            pack2h(Xc[0][i][sig], Xc[1][i][sig], h, l);
            g_oph[obase + ((size_t)i << 10)] = h;
            g_opl[obase + ((size_t)i << 10)] = l;
        }
        __syncthreads();
    }
}

// ---------------------------------------------------------------------------
extern "C" void kernel_launch(void* const* d_in, const int* in_sizes, int n_in,
                              void* d_out, int out_size)
{
    (void)in_sizes; (void)n_in; (void)out_size;
    const float* x   = (const float*)d_in[0];
    const float* qw  = (const float*)d_in[1];
    const float* qb  = (const float*)d_in[2];
    const float* kvw = (const float*)d_in[3];
    const float* kvb = (const float*)d_in[4];
    const float* pw  = (const float*)d_in[5];
    const float* pb  = (const float*)d_in[6];
    const float* ls  = (const float*)d_in[7];
    float* out = (float*)d_out;

    static bool attr_set = false;
    if (!attr_set) {
        cudaFuncSetAttribute((const void*)qkv_mma,
                             cudaFuncAttributeMaxDynamicSharedMemorySize, SMEM_3BUF);
        attr_set = true;
    }

    pack_w        <<<576, 256>>>(qw, kvw, pw);
    cvt_x         <<<dim3(32, 128, 2), 256>>>(x);
    qkv_mma       <<<dim3(5, 256, 2), 256, SMEM_3BUF>>>(qb, kvb);
    scores_mma    <<<dim3(64, 16), 128>>>();
    softmax_kernel<<<16, 1024>>>();
    av_kernel     <<<dim3(32, 16), 256>>>();
    proj_mma      <<<dim3(2, 256, 2), 256>>>(pb, ls, out);
}